// round 6
// baseline (speedup 1.0000x reference)
#include <cuda_runtime.h>

// Problem constants: B=64, D=2048, UNITS=1024, NW=64
#define Dd     2048
#define UNITSn 1024
#define NWn    64

#define UPC    8                 // units per CTA
#define NCTA   (UNITSn / UPC)    // 128 CTAs
#define BKt    128               // k-tile width
#define NT     (Dd / BKt)        // 16 tiles
#define NTHR   512               // 16 warps
#define NWARP  16
#define STAGES 3                 // per-warp private pipeline stages
#define RSTR   12                // xs row stride in floats (48B): conflict-free LDS.128
#define STAGEF (64 * RSTR)       // floats per stage (768)
#define WSLICE (STAGES * STAGEF) // floats per warp slice (2304)

__device__ __forceinline__ void fma2(unsigned long long& d,
                                     unsigned long long a,
                                     unsigned long long b) {
    asm("fma.rn.f32x2 %0, %1, %2, %0;" : "+l"(d) : "l"(a), "l"(b));
}
__device__ __forceinline__ void cp16(unsigned s, const void* g) {
    asm volatile("cp.async.cg.shared.global [%0], [%1], 16;" :: "r"(s), "l"(g));
}
__device__ __forceinline__ void cp_commit() {
    asm volatile("cp.async.commit_group;");
}
template <int N> __device__ __forceinline__ void cp_wait() {
    asm volatile("cp.async.wait_group %0;" :: "n"(N));
}
__device__ __forceinline__ unsigned mdiv(unsigned e, unsigned magic) {
    return (unsigned)(((unsigned long long)e * magic) >> 32);
}

// Per-warp x strip prefetch: this thread loads EXACTLY the bytes it will
// consume (rows lane, lane+32; k-columns z*8..z*8+7 of tile t). Each 32B row
// piece is one aligned L2 sector. Producer==consumer => cp.async.wait_group
// is the only synchronization the GEMM loop needs.
__device__ __forceinline__ void load_strip(const float* __restrict__ xrow0,
                                           unsigned dst_u32, int t) {
    const float* s0 = xrow0 + t * BKt;                 // row `lane`
    const float* s1 = s0 + 32 * Dd;                    // row `lane+32`
    cp16(dst_u32,                      s0);
    cp16(dst_u32 + 16,                 s0 + 4);
    cp16(dst_u32 + 32 * RSTR * 4,      s1);
    cp16(dst_u32 + 32 * RSTR * 4 + 16, s1 + 4);
    cp_commit();
}

// ---------------------------------------------------------------------------
// Fused hashed-linear: build 8 W rows (8x2048 fp32) in smem from index lists,
// then a barrier-free GEMM: each warp owns k-segment z*8 per 128-tile and
// streams its private x strips through a 3-stage cp.async ring. W smem reads
// are warp-uniform broadcasts (x smem elements read exactly once each).
// 3 __syncthreads total in the kernel. No atomics, no scratch, one launch.
// ---------------------------------------------------------------------------
__global__ __launch_bounds__(NTHR, 1) void fused_kernel(const float* __restrict__ x,
                                                        const float* __restrict__ w,
                                                        const float* __restrict__ bias,
                                                        const int* __restrict__ indices,
                                                        float* __restrict__ out,
                                                        int L, unsigned magicL) {
    extern __shared__ float sm[];
    float* ws  = sm;                          // [UPC][Dd]  64 KB (reused as reduce buf)
    float* xs  = sm + UPC * Dd;               // [NWARP][STAGES][64][RSTR]  144 KB
    float* wsm = xs + NWARP * WSLICE;         // [NWn]

    const int tid  = threadIdx.x;
    const int lane = tid & 31;
    const int z    = tid >> 5;                // warp id = k-segment
    const int u0   = blockIdx.x * UPC;

    const float* xrow0 = x + (long)lane * Dd + z * 8;   // this thread's k-strip base
    float* myslice = xs + z * WSLICE + lane * RSTR;
    const unsigned my_u32 = (unsigned)__cvta_generic_to_shared(myslice);

    // Prefetch tiles 0 and 1 into private stages (overlaps all of phase 1).
    load_strip(xrow0, my_u32,              0);
    load_strip(xrow0, my_u32 + STAGEF * 4, 1);

    // ---- Phase 1: build W rows in smem (int4-vectorized, 8 LDG.128 in flight) ----
    if (tid < NWn) wsm[tid] = w[tid];
    const float4 z4 = make_float4(0.f, 0.f, 0.f, 0.f);
    #pragma unroll
    for (int i = 0; i < 8; i++) ((float4*)ws)[i * NTHR + tid] = z4;  // zero 64KB
    __syncthreads();

    {
        const int NWL4 = 16 * L;                       // int4 count per unit
        const int4* ind4 = (const int4*)indices + (long)u0 * NWL4;
        for (int e4 = tid; e4 < NWL4; e4 += NTHR) {
            int4 v[UPC];
            #pragma unroll
            for (int uu = 0; uu < UPC; uu++)
                v[uu] = __ldg(ind4 + (long)uu * NWL4 + e4);
            const int e = e4 * 4;
            const unsigned k0 = mdiv(e,     magicL);
            const unsigned k1 = mdiv(e + 1, magicL);
            const unsigned k2 = mdiv(e + 2, magicL);
            const unsigned k3 = mdiv(e + 3, magicL);
            #pragma unroll
            for (int uu = 0; uu < UPC; uu++) {
                float* wrow = ws + uu * Dd;
                unsigned p;
                p = (unsigned)(v[uu].x - 1); if (p < (unsigned)Dd) wrow[p] = wsm[k0];
                p = (unsigned)(v[uu].y - 1); if (p < (unsigned)Dd) wrow[p] = wsm[k1];
                p = (unsigned)(v[uu].z - 1); if (p < (unsigned)Dd) wrow[p] = wsm[k2];
                p = (unsigned)(v[uu].w - 1); if (p < (unsigned)Dd) wrow[p] = wsm[k3];
            }
        }
    }
    __syncthreads();   // ws ready; from here warps are fully independent

    // ---- Phase 2: barrier-free pipelined GEMM ----
    unsigned long long acc[2][UPC];
    #pragma unroll
    for (int r = 0; r < 2; r++)
        #pragma unroll
        for (int j = 0; j < UPC; j++) acc[r][j] = 0ULL;   // (0.0f, 0.0f)

    const float* wb0 = ws + z * 8;

    #pragma unroll 4
    for (int t = 0; t < NT; t++) {
        if (t < NT - 1) cp_wait<1>(); else cp_wait<0>();

        // Refill stage (t+2)%3 — this thread finished tile t-1 last iteration.
        if (t + 2 < NT)
            load_strip(xrow0, my_u32 + ((t + 2) % STAGES) * STAGEF * 4, t + 2);

        const float* xb = myslice + (t % STAGES) * STAGEF;
        ulonglong2 xv0  = *(const ulonglong2*)(xb);                  // row lane,   k..k+3
        ulonglong2 xv0b = *(const ulonglong2*)(xb + 4);              // row lane,   k+4..k+7
        ulonglong2 xv1  = *(const ulonglong2*)(xb + 32 * RSTR);      // row lane+32
        ulonglong2 xv1b = *(const ulonglong2*)(xb + 32 * RSTR + 4);

        const float* wb = wb0 + t * BKt;
        #pragma unroll
        for (int j = 0; j < UPC; j++) {
            ulonglong2 wva = *(const ulonglong2*)(wb + j * Dd);      // warp-uniform
            ulonglong2 wvb = *(const ulonglong2*)(wb + j * Dd + 4);
            fma2(acc[0][j], xv0.x,  wva.x);
            fma2(acc[0][j], xv0.y,  wva.y);
            fma2(acc[0][j], xv0b.x, wvb.x);
            fma2(acc[0][j], xv0b.y, wvb.y);
            fma2(acc[1][j], xv1.x,  wva.x);
            fma2(acc[1][j], xv1.y,  wva.y);
            fma2(acc[1][j], xv1b.x, wvb.x);
            fma2(acc[1][j], xv1b.y, wvb.y);
        }
    }
    __syncthreads();   // all ws reads done; safe to overlay reduce buffer

    // ---- Cross-z reduction (overlay ws) + bias + store ----
    float* red = ws;   // [16][64][UPC] = 32KB
    #pragma unroll
    for (int r = 0; r < 2; r++) {
        const int b = lane + 32 * r;
        #pragma unroll
        for (int j = 0; j < UPC; j += 2) {
            unsigned long long v0 = acc[r][j], v1 = acc[r][j + 1];
            float s0 = __uint_as_float((unsigned)(v0 & 0xffffffffu)) +
                       __uint_as_float((unsigned)(v0 >> 32));
            float s1 = __uint_as_float((unsigned)(v1 & 0xffffffffu)) +
                       __uint_as_float((unsigned)(v1 >> 32));
            *(float2*)(red + (z * 64 + b) * UPC + j) = make_float2(s0, s1);
        }
    }
    __syncthreads();

    // 512 outputs per CTA, one per thread: b = tid>>3, j = tid&7.
    const int b2 = tid >> 3;
    const int jj = tid & 7;
    float s = 0.f;
    #pragma unroll
    for (int zz = 0; zz < NWARP; zz++)
        s += red[(zz * 64 + b2) * UPC + jj];
    s += __ldg(bias + u0 + jj);
    out[(long)b2 * UNITSn + u0 + jj] = s;
}

// ---------------------------------------------------------------------------
extern "C" void kernel_launch(void* const* d_in, const int* in_sizes, int n_in,
                              void* d_out, int out_size) {
    const float* x       = (const float*)d_in[0];
    const float* w       = (const float*)d_in[1];
    const float* bias    = (const float*)d_in[2];
    const int*   indices = (const int*)d_in[3];
    float*       out     = (float*)d_out;

    const int L = in_sizes[3] / (UNITSn * NWn);
    const unsigned magicL =
        (unsigned)((0x100000000ULL + (unsigned long long)L - 1) / (unsigned long long)L);

    const int smem_bytes =
        (UPC * Dd + NWARP * WSLICE + NWn) * (int)sizeof(float);  // 213,248 B
    cudaFuncSetAttribute(fused_kernel, cudaFuncAttributeMaxDynamicSharedMemorySize,
                         smem_bytes);

    fused_kernel<<<NCTA, NTHR, smem_bytes>>>(x, w, bias, indices, out, L, magicL);
}

// round 7
// speedup vs baseline: 1.9637x; 1.9637x over previous
#include <cuda_runtime.h>

// Problem constants: B=64, D=2048, UNITS=1024, NW=64
#define Dd     2048
#define UNITSn 1024
#define NWn    64

#define UPC    8                 // units per CTA
#define NCTA   (UNITSn / UPC)    // 128 CTAs
#define BKt    128               // k-tile width
#define NT     (Dd / BKt)        // 16 tiles
#define NTHR   512               // 16 warps
#define RPAD   33                // reduce-buffer row stride (conflict-free)

__device__ __forceinline__ void fma2(unsigned long long& d,
                                     unsigned long long a,
                                     unsigned long long b) {
    asm("fma.rn.f32x2 %0, %1, %2, %0;" : "+l"(d) : "l"(a), "l"(b));
}
__device__ __forceinline__ unsigned mdiv(unsigned e, unsigned magic) {
    return (unsigned)(((unsigned long long)e * magic) >> 32);
}

// ---------------------------------------------------------------------------
// Fused hashed-linear.
// Phase 1: build 8 dense W rows (8 x 2048 fp32, 64KB) in smem from the hashed
//          index lists (int4 loads, 8 LDG.128 in flight per thread).
// Phase 2: barrier-free GEMM. Warp z owns batch rows {z,z+16,z+32,z+48}; lane
//          owns k-offset 4*lane of each 128-wide k-tile. x is read DIRECTLY
//          from L2 (512KB, fully L2-resident) via coalesced LDG.128 with a
//          1-tile software pipeline — no x smem, no barriers, no cp.async.
//          W comes from smem as conflict-free per-lane LDS.128.
// Epilogue: padded-smem lane reduction (k is split across lanes), + bias.
// ---------------------------------------------------------------------------
__global__ __launch_bounds__(NTHR, 1) void fused_kernel(const float* __restrict__ x,
                                                        const float* __restrict__ w,
                                                        const float* __restrict__ bias,
                                                        const int* __restrict__ indices,
                                                        float* __restrict__ out,
                                                        int L, unsigned magicL) {
    extern __shared__ float sm[];
    float* ws  = sm;                 // [UPC][Dd] = 64KB  (overlaid by reduce buf later)
    float* wsm = sm + UPC * Dd;      // [NWn]             (dead after phase 1)

    const int tid  = threadIdx.x;
    const int lane = tid & 31;
    const int z    = tid >> 5;                // warp id
    const int u0   = blockIdx.x * UPC;

    // ---- Phase 1: build W rows in smem ----
    if (tid < NWn) wsm[tid] = w[tid];
    const float4 z4 = make_float4(0.f, 0.f, 0.f, 0.f);
    #pragma unroll
    for (int i = 0; i < 8; i++) ((float4*)ws)[i * NTHR + tid] = z4;  // zero 64KB
    __syncthreads();

    {
        const int NWL4 = 16 * L;                       // int4 count per unit
        const int4* ind4 = (const int4*)indices + (long)u0 * NWL4;
        for (int e4 = tid; e4 < NWL4; e4 += NTHR) {
            int4 v[UPC];
            #pragma unroll
            for (int uu = 0; uu < UPC; uu++)
                v[uu] = __ldg(ind4 + (long)uu * NWL4 + e4);
            const int e = e4 * 4;
            const unsigned k0 = mdiv(e,     magicL);
            const unsigned k1 = mdiv(e + 1, magicL);
            const unsigned k2 = mdiv(e + 2, magicL);
            const unsigned k3 = mdiv(e + 3, magicL);
            #pragma unroll
            for (int uu = 0; uu < UPC; uu++) {
                float* wrow = ws + uu * Dd;
                unsigned p;
                p = (unsigned)(v[uu].x - 1); if (p < (unsigned)Dd) wrow[p] = wsm[k0];
                p = (unsigned)(v[uu].y - 1); if (p < (unsigned)Dd) wrow[p] = wsm[k1];
                p = (unsigned)(v[uu].z - 1); if (p < (unsigned)Dd) wrow[p] = wsm[k2];
                p = (unsigned)(v[uu].w - 1); if (p < (unsigned)Dd) wrow[p] = wsm[k3];
            }
        }
    }
    __syncthreads();   // ws ready; mainloop is barrier-free from here

    // ---- Phase 2: GEMM, x direct from L2 ----
    const int koff = lane * 4;                         // this lane's k offset in a tile
    const float* xrow[4];
    #pragma unroll
    for (int r = 0; r < 4; r++)
        xrow[r] = x + (long)(z + 16 * r) * Dd + koff;

    unsigned long long acc[4][UPC];
    #pragma unroll
    for (int r = 0; r < 4; r++)
        #pragma unroll
        for (int j = 0; j < UPC; j++) acc[r][j] = 0ULL;    // (0.0f, 0.0f)

    // Prologue: load tile 0.
    ulonglong2 xa[4];
    #pragma unroll
    for (int r = 0; r < 4; r++) xa[r] = *(const ulonglong2*)(xrow[r]);

    #pragma unroll 2
    for (int t = 0; t < NT; t++) {
        // Software pipeline: issue next tile's 4 coalesced LDG.128 first.
        ulonglong2 xb[4];
        if (t + 1 < NT) {
            #pragma unroll
            for (int r = 0; r < 4; r++)
                xb[r] = *(const ulonglong2*)(xrow[r] + (t + 1) * BKt);
        }

        const float* wk = ws + t * BKt + koff;
        #pragma unroll
        for (int j = 0; j < UPC; j++) {
            ulonglong2 wv = *(const ulonglong2*)(wk + j * Dd);   // conflict-free LDS.128
            #pragma unroll
            for (int r = 0; r < 4; r++) {
                fma2(acc[r][j], xa[r].x, wv.x);   // k, k+1
                fma2(acc[r][j], xa[r].y, wv.y);   // k+2, k+3
            }
        }
        #pragma unroll
        for (int r = 0; r < 4; r++) xa[r] = xb[r];
    }
    __syncthreads();   // all ws reads done; safe to overlay reduce buffer

    // ---- Epilogue: cross-lane k-reduction via padded smem, + bias ----
    float* red = sm;   // [16*32][RPAD] = 67.6KB (overlays ws + wsm)
    #pragma unroll
    for (int r = 0; r < 4; r++)
        #pragma unroll
        for (int j = 0; j < UPC; j++) {
            unsigned long long v = acc[r][j];
            float s = __uint_as_float((unsigned)(v & 0xffffffffu)) +
                      __uint_as_float((unsigned)(v >> 32));
            red[(z * 32 + lane) * RPAD + r * UPC + j] = s;   // banks differ per lane
        }
    __syncthreads();

    // One output per thread: oz = producing warp, rj = (r,j) slot.
    const int oz = tid >> 5;
    const int rj = tid & 31;
    float s = 0.f;
    #pragma unroll
    for (int l = 0; l < 32; l++)
        s += red[(oz * 32 + l) * RPAD + rj];
    const int r  = rj >> 3;
    const int j  = rj & 7;
    s += __ldg(bias + u0 + j);
    out[(long)(oz + 16 * r) * UNITSn + u0 + j] = s;
}

// ---------------------------------------------------------------------------
extern "C" void kernel_launch(void* const* d_in, const int* in_sizes, int n_in,
                              void* d_out, int out_size) {
    const float* x       = (const float*)d_in[0];
    const float* w       = (const float*)d_in[1];
    const float* bias    = (const float*)d_in[2];
    const int*   indices = (const int*)d_in[3];
    float*       out     = (float*)d_out;

    const int L = in_sizes[3] / (UNITSn * NWn);
    const unsigned magicL =
        (unsigned)((0x100000000ULL + (unsigned long long)L - 1) / (unsigned long long)L);

    // smem = max(ws + wsm, reduce buffer) = 512*33 floats = 67,584 B
    const int smem_bytes = (NTHR * RPAD) * (int)sizeof(float);
    cudaFuncSetAttribute(fused_kernel, cudaFuncAttributeMaxDynamicSharedMemorySize,
                         smem_bytes);

    fused_kernel<<<NCTA, NTHR, smem_bytes>>>(x, w, bias, indices, out, L, magicL);
}